// round 14
// baseline (speedup 1.0000x reference)
#include <cuda_runtime.h>
#include <cstdint>

// Problem dims
#define NIMG 32
#define CCH 16
#define HH 224
#define WW 224
#define HWSZ (HH*WW)          // 50176
#define NPIX (NIMG*HWSZ)      // 1,605,632 pixels
#define TOTAL (NIMG*CCH*HWSZ) // 25,690,112 elements

// Conv tiling: 16x16 pixel tile, 256 threads (8 warps), pure IMMA implicit GEMM.
// K = 144 = 4 x k32 (taps 0-7) + 1 x k16 (tap 8) -- no padding waste.
#define TH 16
#define TW 16
#define GX 14
#define GY 14

// ---------------- scratch (device globals: no allocations allowed) ----------
// Replay-safety: g_maxbits is never reset (atomicMax to the same deterministic
// value is idempotent). g_sumI/g_sumQ start zero (static init) and are re-zeroed
// by k_fin AFTER it consumes them, so every replay accumulates from zero.
__device__ unsigned           g_maxbits;     // max|x| as float bits (all >= 0)
__device__ float              g_stepw;       // weight quant step
__device__ int4               g_wq[16*9];    // packed int8 weights [oc][tap]
__device__ int4               g_xq[NPIX];    // packed int8 activations [n][h][w]
__device__ int                g_acc[TOTAL];  // raw conv accumulators (int32, NCHW)
__device__ unsigned long long g_sumI[16];    // exact global sum of acc
__device__ unsigned long long g_sumQ[16];    // exact global sum of acc^2
__device__ float              g_scale[16];   // fused BN scale (incl. stepx*stepw)
__device__ float              g_bias[16];    // fused BN bias

// ---------------- mma wrappers ----------------------------------------------
__device__ __forceinline__ void mma_s8(int* d, int a0, int a1, int a2, int a3,
                                       int b0, int b1) {
    asm volatile(
        "mma.sync.aligned.m16n8k32.row.col.s32.s8.s8.s32 "
        "{%0,%1,%2,%3},{%4,%5,%6,%7},{%8,%9},{%0,%1,%2,%3};"
        : "+r"(d[0]), "+r"(d[1]), "+r"(d[2]), "+r"(d[3])
        : "r"(a0), "r"(a1), "r"(a2), "r"(a3), "r"(b0), "r"(b1));
}
__device__ __forceinline__ void mma_s8_k16(int* d, int a0, int a1, int b0) {
    asm volatile(
        "mma.sync.aligned.m16n8k16.row.col.s32.s8.s8.s32 "
        "{%0,%1,%2,%3},{%4,%5},{%6},{%0,%1,%2,%3};"
        : "+r"(d[0]), "+r"(d[1]), "+r"(d[2]), "+r"(d[3])
        : "r"(a0), "r"(a1), "r"(b0));
}

// ---------------- k_pre: weight quant (block 0) + global max|x| (all) -------
__global__ void k_pre(const float4* __restrict__ x, const float* __restrict__ w) {
    __shared__ float red[256];
    __shared__ float s_stepw;
    int t = threadIdx.x;

    if (blockIdx.x == 0) {
        // ---- weight max + quantize/pack (replaces k_init) ----
        float m = 0.f;
        for (int i = t; i < 16*16*9; i += 256) m = fmaxf(m, fabsf(w[i]));
        red[t] = m; __syncthreads();
        for (int s = 128; s; s >>= 1) {
            if (t < s) red[t] = fmaxf(red[t], red[t+s]);
            __syncthreads();
        }
        if (t == 0) {
            float sw = __fdiv_rn(red[0], 127.0f);
            g_stepw = sw; s_stepw = sw;
        }
        __syncthreads();
        float sw = s_stepw;
        if (t < 144) {
            int oc = t / 9, tap = t % 9;
            int vals[4];
            #pragma unroll
            for (int g = 0; g < 4; ++g) {
                int packed = 0;
                #pragma unroll
                for (int b = 0; b < 4; ++b) {
                    int c = g*4 + b;
                    float v = w[(oc*16 + c)*9 + tap];
                    float q = rintf(__fdiv_rn(v, sw));
                    q = fminf(fmaxf(q, -127.f), 127.f);
                    int qi = (int)q;
                    packed |= (qi & 0xFF) << (8*b);
                }
                vals[g] = packed;
            }
            g_wq[oc*9 + tap] = make_int4(vals[0], vals[1], vals[2], vals[3]);
        }
        __syncthreads();   // red[] reused below
    }

    // ---- activation max (all blocks) ----
    float m = 0.f;
    int stride = gridDim.x * blockDim.x;
    for (int i = blockIdx.x*blockDim.x + t; i < TOTAL/4; i += stride) {
        float4 v = x[i];
        m = fmaxf(m, fmaxf(fmaxf(fabsf(v.x), fabsf(v.y)), fmaxf(fabsf(v.z), fabsf(v.w))));
    }
    #pragma unroll
    for (int off = 16; off; off >>= 1)
        m = fmaxf(m, __shfl_xor_sync(0xFFFFFFFFu, m, off));
    int lane = t & 31, wp = t >> 5;
    if (lane == 0) red[wp] = m;
    __syncthreads();
    if (t == 0) {
        float mm = red[0];
        #pragma unroll
        for (int i = 1; i < 8; ++i) mm = fmaxf(mm, red[i]);
        atomicMax(&g_maxbits, __float_as_uint(mm));   // idempotent across replays
    }
}

// ---------------- k_xq: quantize x -> packed int8, 4 pixels per thread ------
__global__ void k_xq(const float* __restrict__ x) {
    int p4 = blockIdx.x*blockDim.x + threadIdx.x;
    if (p4 >= NPIX/4) return;
    float sx  = __fdiv_rn(__uint_as_float(g_maxbits), 127.0f);
    float inv = __fdiv_rn(1.0f, sx);
    int n = p4 / (HWSZ/4);
    int rem4 = p4 - n*(HWSZ/4);
    const float* base = x + (size_t)n*(CCH*HWSZ) + rem4*4;
    int out[4][4];
    #pragma unroll
    for (int c = 0; c < 16; ++c) {
        float4 v = *(const float4*)(base + (size_t)c*HWSZ);
        float f[4] = {v.x, v.y, v.z, v.w};
        int g = c >> 2, b = c & 3;
        #pragma unroll
        for (int px = 0; px < 4; ++px) {
            float q = rintf(f[px] * inv);
            q = fminf(fmaxf(q, -127.f), 127.f);
            int qi = (int)q;
            if (b == 0) out[px][g] = (qi & 0xFF);
            else out[px][g] |= (qi & 0xFF) << (8*b);
        }
    }
    int pix = n*HWSZ + rem4*4;
    #pragma unroll
    for (int px = 0; px < 4; ++px)
        g_xq[pix + px] = make_int4(out[px][0], out[px][1], out[px][2], out[px][3]);
}

// ---------------- conv: pure IMMA, 4 x k32 + 1 x k16 ------------------------
__global__ void __launch_bounds__(256, 5) k_conv() {
    __shared__ int4 s_x[18][18];        // halo tile, pixel-major, 5184 B
    __shared__ int4 s_w[16*9];          // weights [oc*9 + tap], 2304 B
    __shared__ int       s_I[8][16];
    __shared__ long long s_Q[8][16];

    int t = threadIdx.x;
    int n = blockIdx.z;
    int h0 = blockIdx.y * TH, w0 = blockIdx.x * TW;

    // load halo tile (zero padded)
    for (int i = t; i < 18*18; i += 256) {
        int r = i / 18, cc = i - r*18;
        int gh = h0 - 1 + r, gw = w0 - 1 + cc;
        int4 v = make_int4(0,0,0,0);
        if ((unsigned)gh < (unsigned)HH && (unsigned)gw < (unsigned)WW)
            v = g_xq[n*HWSZ + gh*WW + gw];
        s_x[r][cc] = v;
    }
    if (t < 144) s_w[t] = g_wq[t];
    __syncthreads();

    int w = t >> 5, l = t & 31;
    int g4 = l >> 2, q = l & 3;          // A/C row group, K word index
    const int* swi = (const int*)s_w;

    int acc[4][4];
    #pragma unroll
    for (int tt = 0; tt < 4; ++tt)
        #pragma unroll
        for (int j = 0; j < 4; ++j) acc[tt][j] = 0;

    #pragma unroll
    for (int kc = 0; kc < 4; ++kc) {
        const int tap0 = 2*kc, tap1 = 2*kc + 1;
        const int dy0 = tap0/3, dx0 = tap0%3;
        const int dy1 = tap1/3, dx1 = tap1%3;
        int a0 = swi[(g4*9     + tap0)*4 + q];
        int a1 = swi[((g4+8)*9 + tap0)*4 + q];
        int a2 = swi[(g4*9     + tap1)*4 + q];
        int a3 = swi[((g4+8)*9 + tap1)*4 + q];
        #pragma unroll
        for (int tt = 0; tt < 4; ++tt) {
            int r0 = 2*w + (tt & 1), c0 = 8*(tt >> 1);
            const int* bp0 = (const int*)&s_x[r0 + dy0][c0 + dx0];
            const int* bp1 = (const int*)&s_x[r0 + dy1][c0 + dx1];
            mma_s8(acc[tt], a0, a1, a2, a3, bp0[l], bp1[l]);
        }
    }
    {   // tap 8 (dy=2, dx=2) via k16 -- no wasted K
        int a0 = swi[(g4*9     + 8)*4 + q];
        int a1 = swi[((g4+8)*9 + 8)*4 + q];
        #pragma unroll
        for (int tt = 0; tt < 4; ++tt) {
            int r0 = 2*w + (tt & 1), c0 = 8*(tt >> 1);
            const int* bp = (const int*)&s_x[r0 + 2][c0 + 2];
            mma_s8_k16(acc[tt], a0, a1, bp[l]);
        }
    }

    // store raw accumulators (int2 per oc-half, coalesced per quad)
    #pragma unroll
    for (int tt = 0; tt < 4; ++tt) {
        int r0 = 2*w + (tt & 1), c0 = 8*(tt >> 1);
        size_t ob = (size_t)n*CCH*HWSZ + (size_t)(h0 + r0)*WW + (w0 + c0 + 2*q);
        *(int2*)(g_acc + ob + (size_t)g4*HWSZ)     = make_int2(acc[tt][0], acc[tt][1]);
        *(int2*)(g_acc + ob + (size_t)(g4+8)*HWSZ) = make_int2(acc[tt][2], acc[tt][3]);
    }

    // exact per-channel integer stats
    int sl = 0, sh = 0;
    long long ql = 0, qh = 0;
    #pragma unroll
    for (int tt = 0; tt < 4; ++tt) {
        sl += acc[tt][0] + acc[tt][1];
        sh += acc[tt][2] + acc[tt][3];
        ql += (long long)acc[tt][0]*acc[tt][0] + (long long)acc[tt][1]*acc[tt][1];
        qh += (long long)acc[tt][2]*acc[tt][2] + (long long)acc[tt][3]*acc[tt][3];
    }
    sl += __shfl_xor_sync(0xFFFFFFFFu, sl, 1);
    sl += __shfl_xor_sync(0xFFFFFFFFu, sl, 2);
    sh += __shfl_xor_sync(0xFFFFFFFFu, sh, 1);
    sh += __shfl_xor_sync(0xFFFFFFFFu, sh, 2);
    ql += __shfl_xor_sync(0xFFFFFFFFu, ql, 1);
    ql += __shfl_xor_sync(0xFFFFFFFFu, ql, 2);
    qh += __shfl_xor_sync(0xFFFFFFFFu, qh, 1);
    qh += __shfl_xor_sync(0xFFFFFFFFu, qh, 2);
    if (q == 0) {
        s_I[w][g4]     = sl;  s_Q[w][g4]     = ql;
        s_I[w][g4 + 8] = sh;  s_Q[w][g4 + 8] = qh;
    }
    __syncthreads();
    if (t < 16) {
        long long ti = 0, tq = 0;
        #pragma unroll
        for (int wp = 0; wp < 8; ++wp) {
            ti += (long long)s_I[wp][t];
            tq += s_Q[wp][t];
        }
        atomicAdd(&g_sumI[t], (unsigned long long)ti);
        atomicAdd(&g_sumQ[t], (unsigned long long)tq);
    }
}

// ---------------- k_fin: BN affine from exact sums, then reset sums ---------
__global__ void k_fin(const float* __restrict__ gamma, const float* __restrict__ beta) {
    int t = threadIdx.x;
    if (t < 16) {
        double stepx = (double)__fdiv_rn(__uint_as_float(g_maxbits), 127.0f);
        double sc = stepx * (double)g_stepw;      // y = sc * acc (exact)
        double M = (double)NPIX;
        double sumI = (double)(long long)g_sumI[t];
        double sumQ = (double)(long long)g_sumQ[t];
        double mean = sc * sumI / M;
        double ey2  = sc * sc * sumQ / M;
        double var  = ey2 - mean*mean;
        double inv  = (double)gamma[t] / sqrt(var + 1e-5);
        g_scale[t] = (float)(sc * inv);
        g_bias[t]  = (float)((double)beta[t] - mean * inv);
        // reset accumulators for the next graph replay (consumed above)
        g_sumI[t] = 0ull;
        g_sumQ[t] = 0ull;
    }
}

// ---------------- k_epi: memory-bound affine epilogue (L2-aware order) ------
// Planes processed in REVERSE write order so epi starts on conv's most
// recently written (still L2-resident) accumulators.
__global__ void k_epi(float* __restrict__ out) {
    int plane = (NIMG*CCH - 1) - blockIdx.y;   // reverse: n=31 first
    int c = plane & 15;
    float sc = g_scale[c], bi = g_bias[c];
    int i = blockIdx.x * blockDim.x + threadIdx.x;
    size_t base = (size_t)plane * HWSZ + (size_t)i * 4;
    int4 a = *(const int4*)(g_acc + base);
    float4 v;
    v.x = fminf(fmaxf(fmaf((float)a.x, sc, bi), 0.f), 6.f);
    v.y = fminf(fmaxf(fmaf((float)a.y, sc, bi), 0.f), 6.f);
    v.z = fminf(fmaxf(fmaf((float)a.z, sc, bi), 0.f), 6.f);
    v.w = fminf(fmaxf(fmaf((float)a.w, sc, bi), 0.f), 6.f);
    *(float4*)(out + base) = v;
}

// ---------------- launch ----------------------------------------------------
extern "C" void kernel_launch(void* const* d_in, const int* in_sizes, int n_in,
                              void* d_out, int out_size) {
    const float* x     = (const float*)d_in[0];
    const float* wgt   = (const float*)d_in[1];
    const float* gamma = (const float*)d_in[2];
    const float* beta  = (const float*)d_in[3];
    float* out = (float*)d_out;

    k_pre<<<1184, 256>>>((const float4*)x, wgt);
    k_xq<<<(NPIX/4 + 255)/256, 256>>>(x);
    dim3 g(GX, GY, NIMG);
    k_conv<<<g, 256>>>();
    k_fin<<<1, 32>>>(gamma, beta);
    dim3 ge(HWSZ/4/256, NIMG*CCH);       // (49, 512)
    k_epi<<<ge, 256>>>(out);
}

// round 15
// speedup vs baseline: 1.0143x; 1.0143x over previous
#include <cuda_runtime.h>
#include <cstdint>

// Problem dims
#define NIMG 32
#define CCH 16
#define HH 224
#define WW 224
#define HWSZ (HH*WW)          // 50176
#define NPIX (NIMG*HWSZ)      // 1,605,632 pixels
#define TOTAL (NIMG*CCH*HWSZ) // 25,690,112 elements

// Conv tiling: 16x16 pixel tile, 256 threads (8 warps), pure IMMA implicit GEMM.
// K = 144 = 4 x k32 (taps 0-7) + 1 x k16 (tap 8) -- no padding waste.
#define TH 16
#define TW 16
#define GX 14
#define GY 14
#define NBLK (GX*GY*NIMG)     // 6272 conv blocks

// ---------------- scratch (device globals: no allocations allowed) ----------
// Replay-safety: g_maxbits is never reset (atomicMax of the same deterministic
// value is idempotent). g_sumI/g_sumQ/g_ctr start zero (static init) and are
// re-zeroed by the tail conv block AFTER consuming them.
__device__ unsigned           g_maxbits;     // max|x| as float bits (all >= 0)
__device__ float              g_stepw;       // weight quant step
__device__ int4               g_wq[16*9];    // packed int8 weights [oc][tap]
__device__ int4               g_xq[NPIX];    // packed int8 activations [n][h][w]
__device__ int                g_acc[TOTAL];  // raw conv accumulators (int32, NCHW)
__device__ unsigned long long g_sumI[16];    // exact global sum of acc
__device__ unsigned long long g_sumQ[16];    // exact global sum of acc^2
__device__ unsigned           g_ctr;         // conv blocks-done counter
__device__ float              g_scale[16];   // fused BN scale (incl. stepx*stepw)
__device__ float              g_bias[16];    // fused BN bias

// ---------------- mma wrappers ----------------------------------------------
__device__ __forceinline__ void mma_s8(int* d, int a0, int a1, int a2, int a3,
                                       int b0, int b1) {
    asm volatile(
        "mma.sync.aligned.m16n8k32.row.col.s32.s8.s8.s32 "
        "{%0,%1,%2,%3},{%4,%5,%6,%7},{%8,%9},{%0,%1,%2,%3};"
        : "+r"(d[0]), "+r"(d[1]), "+r"(d[2]), "+r"(d[3])
        : "r"(a0), "r"(a1), "r"(a2), "r"(a3), "r"(b0), "r"(b1));
}
__device__ __forceinline__ void mma_s8_k16(int* d, int a0, int a1, int b0) {
    asm volatile(
        "mma.sync.aligned.m16n8k16.row.col.s32.s8.s8.s32 "
        "{%0,%1,%2,%3},{%4,%5},{%6},{%0,%1,%2,%3};"
        : "+r"(d[0]), "+r"(d[1]), "+r"(d[2]), "+r"(d[3])
        : "r"(a0), "r"(a1), "r"(b0));
}

// ---------------- k_pre: weight quant (block 0) + global max|x| (all) -------
__global__ void k_pre(const float4* __restrict__ x, const float* __restrict__ w) {
    __shared__ float red[256];
    __shared__ float s_stepw;
    int t = threadIdx.x;

    if (blockIdx.x == 0) {
        // ---- weight max + quantize/pack ----
        float m = 0.f;
        for (int i = t; i < 16*16*9; i += 256) m = fmaxf(m, fabsf(w[i]));
        red[t] = m; __syncthreads();
        for (int s = 128; s; s >>= 1) {
            if (t < s) red[t] = fmaxf(red[t], red[t+s]);
            __syncthreads();
        }
        if (t == 0) {
            float sw = __fdiv_rn(red[0], 127.0f);
            g_stepw = sw; s_stepw = sw;
        }
        __syncthreads();
        float sw = s_stepw;
        if (t < 144) {
            int oc = t / 9, tap = t % 9;
            int vals[4];
            #pragma unroll
            for (int g = 0; g < 4; ++g) {
                int packed = 0;
                #pragma unroll
                for (int b = 0; b < 4; ++b) {
                    int c = g*4 + b;
                    float v = w[(oc*16 + c)*9 + tap];
                    float q = rintf(__fdiv_rn(v, sw));
                    q = fminf(fmaxf(q, -127.f), 127.f);
                    int qi = (int)q;
                    packed |= (qi & 0xFF) << (8*b);
                }
                vals[g] = packed;
            }
            g_wq[oc*9 + tap] = make_int4(vals[0], vals[1], vals[2], vals[3]);
        }
        __syncthreads();   // red[] reused below
    }

    // ---- activation max (all blocks) ----
    float m = 0.f;
    int stride = gridDim.x * blockDim.x;
    for (int i = blockIdx.x*blockDim.x + t; i < TOTAL/4; i += stride) {
        float4 v = x[i];
        m = fmaxf(m, fmaxf(fmaxf(fabsf(v.x), fabsf(v.y)), fmaxf(fabsf(v.z), fabsf(v.w))));
    }
    #pragma unroll
    for (int off = 16; off; off >>= 1)
        m = fmaxf(m, __shfl_xor_sync(0xFFFFFFFFu, m, off));
    int lane = t & 31, wp = t >> 5;
    if (lane == 0) red[wp] = m;
    __syncthreads();
    if (t == 0) {
        float mm = red[0];
        #pragma unroll
        for (int i = 1; i < 8; ++i) mm = fmaxf(mm, red[i]);
        atomicMax(&g_maxbits, __float_as_uint(mm));   // idempotent across replays
    }
}

// ---------------- k_xq: quantize x -> packed int8, 4 pixels per thread ------
__global__ void k_xq(const float* __restrict__ x) {
    int p4 = blockIdx.x*blockDim.x + threadIdx.x;
    if (p4 >= NPIX/4) return;
    float sx  = __fdiv_rn(__uint_as_float(g_maxbits), 127.0f);
    float inv = __fdiv_rn(1.0f, sx);
    int n = p4 / (HWSZ/4);
    int rem4 = p4 - n*(HWSZ/4);
    const float* base = x + (size_t)n*(CCH*HWSZ) + rem4*4;
    int out[4][4];
    #pragma unroll
    for (int c = 0; c < 16; ++c) {
        float4 v = *(const float4*)(base + (size_t)c*HWSZ);
        float f[4] = {v.x, v.y, v.z, v.w};
        int g = c >> 2, b = c & 3;
        #pragma unroll
        for (int px = 0; px < 4; ++px) {
            float q = rintf(f[px] * inv);
            q = fminf(fmaxf(q, -127.f), 127.f);
            int qi = (int)q;
            if (b == 0) out[px][g] = (qi & 0xFF);
            else out[px][g] |= (qi & 0xFF) << (8*b);
        }
    }
    int pix = n*HWSZ + rem4*4;
    #pragma unroll
    for (int px = 0; px < 4; ++px)
        g_xq[pix + px] = make_int4(out[px][0], out[px][1], out[px][2], out[px][3]);
}

// ---------------- conv: pure IMMA + tail-block BN finalize ------------------
__global__ void __launch_bounds__(256, 5) k_conv(const float* __restrict__ gamma,
                                                 const float* __restrict__ beta) {
    __shared__ int4 s_x[18][18];        // halo tile, pixel-major, 5184 B
    __shared__ int4 s_w[16*9];          // weights [oc*9 + tap], 2304 B
    __shared__ int       s_I[8][16];
    __shared__ long long s_Q[8][16];
    __shared__ bool      s_last;

    int t = threadIdx.x;
    int n = blockIdx.z;
    int h0 = blockIdx.y * TH, w0 = blockIdx.x * TW;

    // load halo tile (zero padded)
    for (int i = t; i < 18*18; i += 256) {
        int r = i / 18, cc = i - r*18;
        int gh = h0 - 1 + r, gw = w0 - 1 + cc;
        int4 v = make_int4(0,0,0,0);
        if ((unsigned)gh < (unsigned)HH && (unsigned)gw < (unsigned)WW)
            v = g_xq[n*HWSZ + gh*WW + gw];
        s_x[r][cc] = v;
    }
    if (t < 144) s_w[t] = g_wq[t];
    __syncthreads();

    int w = t >> 5, l = t & 31;
    int g4 = l >> 2, q = l & 3;          // A/C row group, K word index
    const int* swi = (const int*)s_w;

    int acc[4][4];
    #pragma unroll
    for (int tt = 0; tt < 4; ++tt)
        #pragma unroll
        for (int j = 0; j < 4; ++j) acc[tt][j] = 0;

    #pragma unroll
    for (int kc = 0; kc < 4; ++kc) {
        const int tap0 = 2*kc, tap1 = 2*kc + 1;
        const int dy0 = tap0/3, dx0 = tap0%3;
        const int dy1 = tap1/3, dx1 = tap1%3;
        int a0 = swi[(g4*9     + tap0)*4 + q];
        int a1 = swi[((g4+8)*9 + tap0)*4 + q];
        int a2 = swi[(g4*9     + tap1)*4 + q];
        int a3 = swi[((g4+8)*9 + tap1)*4 + q];
        #pragma unroll
        for (int tt = 0; tt < 4; ++tt) {
            int r0 = 2*w + (tt & 1), c0 = 8*(tt >> 1);
            const int* bp0 = (const int*)&s_x[r0 + dy0][c0 + dx0];
            const int* bp1 = (const int*)&s_x[r0 + dy1][c0 + dx1];
            mma_s8(acc[tt], a0, a1, a2, a3, bp0[l], bp1[l]);
        }
    }
    {   // tap 8 (dy=2, dx=2) via k16 -- no wasted K
        int a0 = swi[(g4*9     + 8)*4 + q];
        int a1 = swi[((g4+8)*9 + 8)*4 + q];
        #pragma unroll
        for (int tt = 0; tt < 4; ++tt) {
            int r0 = 2*w + (tt & 1), c0 = 8*(tt >> 1);
            const int* bp = (const int*)&s_x[r0 + 2][c0 + 2];
            mma_s8_k16(acc[tt], a0, a1, bp[l]);
        }
    }

    // store raw accumulators (int2 per oc-half, coalesced per quad)
    #pragma unroll
    for (int tt = 0; tt < 4; ++tt) {
        int r0 = 2*w + (tt & 1), c0 = 8*(tt >> 1);
        size_t ob = (size_t)n*CCH*HWSZ + (size_t)(h0 + r0)*WW + (w0 + c0 + 2*q);
        *(int2*)(g_acc + ob + (size_t)g4*HWSZ)     = make_int2(acc[tt][0], acc[tt][1]);
        *(int2*)(g_acc + ob + (size_t)(g4+8)*HWSZ) = make_int2(acc[tt][2], acc[tt][3]);
    }

    // exact per-channel integer stats
    int sl = 0, sh = 0;
    long long ql = 0, qh = 0;
    #pragma unroll
    for (int tt = 0; tt < 4; ++tt) {
        sl += acc[tt][0] + acc[tt][1];
        sh += acc[tt][2] + acc[tt][3];
        ql += (long long)acc[tt][0]*acc[tt][0] + (long long)acc[tt][1]*acc[tt][1];
        qh += (long long)acc[tt][2]*acc[tt][2] + (long long)acc[tt][3]*acc[tt][3];
    }
    sl += __shfl_xor_sync(0xFFFFFFFFu, sl, 1);
    sl += __shfl_xor_sync(0xFFFFFFFFu, sl, 2);
    sh += __shfl_xor_sync(0xFFFFFFFFu, sh, 1);
    sh += __shfl_xor_sync(0xFFFFFFFFu, sh, 2);
    ql += __shfl_xor_sync(0xFFFFFFFFu, ql, 1);
    ql += __shfl_xor_sync(0xFFFFFFFFu, ql, 2);
    qh += __shfl_xor_sync(0xFFFFFFFFu, qh, 1);
    qh += __shfl_xor_sync(0xFFFFFFFFu, qh, 2);
    if (q == 0) {
        s_I[w][g4]     = sl;  s_Q[w][g4]     = ql;
        s_I[w][g4 + 8] = sh;  s_Q[w][g4 + 8] = qh;
    }
    __syncthreads();
    if (t < 16) {
        long long ti = 0, tq = 0;
        #pragma unroll
        for (int wp = 0; wp < 8; ++wp) {
            ti += (long long)s_I[wp][t];
            tq += s_Q[wp][t];
        }
        atomicAdd(&g_sumI[t], (unsigned long long)ti);
        atomicAdd(&g_sumQ[t], (unsigned long long)tq);
    }

    // ---- tail-block BN finalize (replaces k_fin launch) ----
    if (t == 0) {
        __threadfence();                               // publish our atomics
        unsigned prev = atomicAdd(&g_ctr, 1u);
        s_last = (prev == (unsigned)(NBLK - 1));
    }
    __syncthreads();
    if (s_last) {
        if (t < 16) {
            double stepx = (double)__fdiv_rn(__uint_as_float(g_maxbits), 127.0f);
            double sc = stepx * (double)g_stepw;       // y = sc * acc (exact)
            double M = (double)NPIX;
            double sumI = (double)(long long)g_sumI[t];
            double sumQ = (double)(long long)g_sumQ[t];
            double mean = sc * sumI / M;
            double ey2  = sc * sc * sumQ / M;
            double var  = ey2 - mean*mean;
            double inv  = (double)gamma[t] / sqrt(var + 1e-5);
            g_scale[t] = (float)(sc * inv);
            g_bias[t]  = (float)((double)beta[t] - mean * inv);
            // reset for next graph replay (consumed above)
            g_sumI[t] = 0ull;
            g_sumQ[t] = 0ull;
        }
        if (t == 0) g_ctr = 0u;
    }
}

// ---------------- k_epi: memory-bound affine epilogue (L2-aware order) ------
// Planes processed in REVERSE write order so epi starts on conv's most
// recently written (still L2-resident) accumulators.
__global__ void k_epi(float* __restrict__ out) {
    int plane = (NIMG*CCH - 1) - blockIdx.y;   // reverse: n=31 first
    int c = plane & 15;
    float sc = g_scale[c], bi = g_bias[c];
    int i = blockIdx.x * blockDim.x + threadIdx.x;
    size_t base = (size_t)plane * HWSZ + (size_t)i * 4;
    int4 a = *(const int4*)(g_acc + base);
    float4 v;
    v.x = fminf(fmaxf(fmaf((float)a.x, sc, bi), 0.f), 6.f);
    v.y = fminf(fmaxf(fmaf((float)a.y, sc, bi), 0.f), 6.f);
    v.z = fminf(fmaxf(fmaf((float)a.z, sc, bi), 0.f), 6.f);
    v.w = fminf(fmaxf(fmaf((float)a.w, sc, bi), 0.f), 6.f);
    *(float4*)(out + base) = v;
}

// ---------------- launch ----------------------------------------------------
extern "C" void kernel_launch(void* const* d_in, const int* in_sizes, int n_in,
                              void* d_out, int out_size) {
    const float* x     = (const float*)d_in[0];
    const float* wgt   = (const float*)d_in[1];
    const float* gamma = (const float*)d_in[2];
    const float* beta  = (const float*)d_in[3];
    float* out = (float*)d_out;

    k_pre<<<1184, 256>>>((const float4*)x, wgt);
    k_xq<<<(NPIX/4 + 255)/256, 256>>>(x);
    dim3 g(GX, GY, NIMG);
    k_conv<<<g, 256>>>(gamma, beta);
    dim3 ge(HWSZ/4/256, NIMG*CCH);       // (49, 512)
    k_epi<<<ge, 256>>>(out);
}